// round 5
// baseline (speedup 1.0000x reference)
#include <cuda_runtime.h>

typedef unsigned long long ull;

#define Lg 64
#define Bg 1024
#define TH 16
#define NTILES (Lg/TH)          // 4
#define THREADS 1024
#define R1 (TH+4)               // 20 conv1 output rows (halo 2)
#define R2 (TH+2)               // 18 conv2 output rows (halo 1)
#define RZ (TH+6)               // 22 input rows (halo 3)
#define PW 34                   // pairs per row: p = -1..32 (wrapped halo)

// ---- shared memory layout (ull units) ----
#define S1U 0                               // 16*20*34 = 10880
#define S2U (S1U + 16*R1*PW)                // 10880 (+9792)
#define SZU (S2U + 16*R2*PW)                // 20672 (+748)
#define WU1 (SZU + RZ*PW)                   // 21420 (2304)
#define WU0 (WU1 + 2304)                    // 23724 (144)
#define WU2 (WU0 + 144)                     // 23868 (144)
#define BFU (WU2 + 144)                     // 24012 (biases: 33 floats -> 20 ull)
#define U_TOTAL (BFU + 20)                  // 24032
#define SMEM_BYTES ((size_t)U_TOTAL * 8)    // 192256 B

// ---- packed f32x2 helpers (sm_100+) : per-lane exact fp32 FMA ----
__device__ __forceinline__ ull pk(float lo, float hi) {
    ull r; asm("mov.b64 %0, {%1, %2};" : "=l"(r) : "f"(lo), "f"(hi)); return r;
}
__device__ __forceinline__ void upk(ull v, float& lo, float& hi) {
    asm("mov.b64 {%0, %1}, %2;" : "=f"(lo), "=f"(hi) : "l"(v));
}
__device__ __forceinline__ void fma2(ull& d, ull a, ull b) {
    asm("fma.rn.f32x2 %0, %1, %2, %0;" : "+l"(d) : "l"(a), "l"(b));
}

// XLA EmitFastTanh replica. DO NOT CHANGE (bit-exactness verified).
__device__ __forceinline__ float xla_tanh(float x) {
    float ax = fabsf(x);
    float xc = fminf(fmaxf(x, -9.0f), 9.0f);
    float x2 = __fmul_rn(xc, xc);
    float p = -2.76076847742355e-16f;
    p = __fmaf_rn(p, x2,  2.00018790482477e-13f);
    p = __fmaf_rn(p, x2, -8.60467152213735e-11f);
    p = __fmaf_rn(p, x2,  5.12229709037114e-08f);
    p = __fmaf_rn(p, x2,  1.48572235717979e-05f);
    p = __fmaf_rn(p, x2,  6.37261928875436e-04f);
    p = __fmaf_rn(p, x2,  4.89352455891786e-03f);
    float num = __fmul_rn(xc, p);
    float q =  1.19825839466702e-06f;
    q = __fmaf_rn(q, x2,  1.18534705686654e-04f);
    q = __fmaf_rn(q, x2,  2.26843463243900e-03f);
    q = __fmaf_rn(q, x2,  4.89352518554385e-03f);
    float r = __fdiv_rn(num, q);
    return (ax < 0.0004f) ? x : r;
}

__global__ void copy_k(const float4* __restrict__ in, float4* __restrict__ out) {
    int i = blockIdx.x * blockDim.x + threadIdx.x;
    out[i] = in[i];
}

// One fused layer. All conv accumulations are single fp32 FMA chains from 0
// in k = (dy, dx, ci) order (ci fastest), bias after — bit-identical to XLA.
__global__ void __launch_bounds__(THREADS, 1)
layer_kernel(float* __restrict__ x,
             const float* __restrict__ w0, const float* __restrict__ b0,
             const float* __restrict__ w1, const float* __restrict__ b1,
             const float* __restrict__ w2, const float* __restrict__ b2,
             int parity)
{
    extern __shared__ ull su[];
    float* sb = (float*)(su + BFU);      // sb[0..15]=b0, [16..31]=b1, [32]=b2

    const int tid   = threadIdx.x;
    const int rbase = blockIdx.x * TH;                 // even
    const int xbase = ((int)blockIdx.y) << 12;         // b*4096

    // ---- Phase 0: weights as duplicated (w,w) pairs + biases + packed input ----
    for (int t = tid; t < 2304; t += THREADS) { float w = w1[t]; su[WU1 + t] = pk(w, w); }
    if (tid < 144) {
        float a = w0[tid], b = w2[tid];
        su[WU0 + tid] = pk(a, a);
        su[WU2 + tid] = pk(b, b);
    }
    if (tid >= 160 && tid < 176) { int i = tid - 160; sb[i] = b0[i]; }
    if (tid >= 192 && tid < 208) { int i = tid - 192; sb[16 + i] = b1[i]; }
    if (tid == 224) { sb[32] = b2[0]; }

    // packed masked input: entry e of row rr holds pair p = e-1:
    // ( z[gr][p&63], z[gr][(p+32)&63] ), zeroed at non-A sites.
    if (tid < RZ * PW) {
        int rr = tid / PW, e = tid - rr * PW, p = e - 1;
        int gr = (rbase + rr - 3) & 63;
        int c0 = p & 63, c1 = (p + 32) & 63;
        const float* row = x + xbase + (gr << 6);
        float v0 = row[c0], v1 = row[c1];
        v0 = (((gr + c0) & 1) == parity) ? v0 : 0.0f;
        v1 = (((gr + c1) & 1) == parity) ? v1 : 0.0f;
        su[SZU + tid] = pk(v0, v1);
    }
    __syncthreads();

    // ---- Phase 1: conv1 (1 -> 16), chain (dy,dx), bias, tanh ----
    // pass 1: rows 0..15, 2pp x 4co: 16*16*4 = 1024 tasks (exact)
    {
        int rr = tid >> 6, r6 = tid & 63;
        int pA = (r6 >> 2) & 15, pB = pA + 16;
        int coB = (r6 & 3) << 2;
        ull acc[8];
        #pragma unroll
        for (int i = 0; i < 8; i++) acc[i] = 0ull;
        #pragma unroll
        for (int dy = 0; dy < 3; dy++) {
            const ull* rp = su + SZU + (rr + dy) * PW + 1;
            #pragma unroll
            for (int dx = 0; dx < 3; dx++) {
                ull qa = rp[pA + dx - 1];
                ull qb = rp[pB + dx - 1];
                const ull* wp = su + WU0 + (dy * 3 + dx) * 16 + coB;
                ulonglong2 w01 = *(const ulonglong2*)(wp);
                ulonglong2 w23 = *(const ulonglong2*)(wp + 2);
                fma2(acc[0], w01.x, qa); fma2(acc[1], w01.x, qb);
                fma2(acc[2], w01.y, qa); fma2(acc[3], w01.y, qb);
                fma2(acc[4], w23.x, qa); fma2(acc[5], w23.x, qb);
                fma2(acc[6], w23.y, qa); fma2(acc[7], w23.y, qb);
            }
        }
        #pragma unroll
        for (int j = 0; j < 4; j++) {
            int co = coB + j;
            float bb = sb[co];
            float uA0, uA1, uB0, uB1;
            upk(acc[2*j], uA0, uA1); upk(acc[2*j + 1], uB0, uB1);
            float tA0 = xla_tanh(__fadd_rn(uA0, bb));
            float tA1 = xla_tanh(__fadd_rn(uA1, bb));
            float tB0 = xla_tanh(__fadd_rn(uB0, bb));
            float tB1 = xla_tanh(__fadd_rn(uB1, bb));
            ull* op = su + S1U + (co * R1 + rr) * PW + 1;
            op[pA] = pk(tA0, tA1);
            op[pB] = pk(tB0, tB1);
            if (pA == 15) op[-1] = pk(tB1, tB0);   // halo = swap(pair 31)
            if (pA == 0)  op[32] = pk(tA1, tA0);   // halo = swap(pair 0)
        }
    }
    // pass 2: rows 16..19, 1pp x 4co: 4*32*4 = 512 tasks
    if (tid < 512) {
        int rr = 16 + (tid >> 7), rem = tid & 127;
        int p0 = rem >> 2;
        int coB = (rem & 3) << 2;
        ull acc[4];
        #pragma unroll
        for (int i = 0; i < 4; i++) acc[i] = 0ull;
        #pragma unroll
        for (int dy = 0; dy < 3; dy++) {
            const ull* rp = su + SZU + (rr + dy) * PW + 1;
            #pragma unroll
            for (int dx = 0; dx < 3; dx++) {
                ull qa = rp[p0 + dx - 1];
                const ull* wp = su + WU0 + (dy * 3 + dx) * 16 + coB;
                ulonglong2 w01 = *(const ulonglong2*)(wp);
                ulonglong2 w23 = *(const ulonglong2*)(wp + 2);
                fma2(acc[0], w01.x, qa); fma2(acc[1], w01.y, qa);
                fma2(acc[2], w23.x, qa); fma2(acc[3], w23.y, qa);
            }
        }
        #pragma unroll
        for (int j = 0; j < 4; j++) {
            int co = coB + j;
            float bb = sb[co];
            float u0, u1;
            upk(acc[j], u0, u1);
            float t0 = xla_tanh(__fadd_rn(u0, bb));
            float t1 = xla_tanh(__fadd_rn(u1, bb));
            ull* op = su + S1U + (co * R1 + rr) * PW + 1;
            op[p0] = pk(t0, t1);
            if (p0 == 31) op[-1] = pk(t1, t0);
            if (p0 == 0)  op[32] = pk(t1, t0);
        }
    }
    __syncthreads();

    // ---- Phase 2: conv2 (16 -> 16), chain (dy,dx,ci), bias, tanh ----
    // pass 1: rows 0..15, 2pp x 4co: 16*16*4 = 1024 tasks (exact)
    {
        int rr = tid >> 6, r6 = tid & 63;
        int pA = (r6 >> 2) & 15, pB = pA + 16;
        int coB = (r6 & 3) << 2;
        ull acc[8];
        #pragma unroll
        for (int i = 0; i < 8; i++) acc[i] = 0ull;
        #pragma unroll
        for (int dy = 0; dy < 3; dy++) {
            const ull* rbp = su + S1U + (rr + dy) * PW + 1;
            #pragma unroll
            for (int dx = 0; dx < 3; dx++) {
                const ull* wb = su + WU1 + (dy * 3 + dx) * 256 + coB;
                #pragma unroll 4
                for (int ci = 0; ci < 16; ci++) {
                    const ull* rp = rbp + ci * (R1 * PW);
                    ull qa = rp[pA + dx - 1];
                    ull qb = rp[pB + dx - 1];
                    const ull* wp = wb + ci * 16;
                    ulonglong2 w01 = *(const ulonglong2*)(wp);
                    ulonglong2 w23 = *(const ulonglong2*)(wp + 2);
                    fma2(acc[0], w01.x, qa); fma2(acc[1], w01.x, qb);
                    fma2(acc[2], w01.y, qa); fma2(acc[3], w01.y, qb);
                    fma2(acc[4], w23.x, qa); fma2(acc[5], w23.x, qb);
                    fma2(acc[6], w23.y, qa); fma2(acc[7], w23.y, qb);
                }
            }
        }
        #pragma unroll
        for (int j = 0; j < 4; j++) {
            int co = coB + j;
            float bb = sb[16 + co];
            float uA0, uA1, uB0, uB1;
            upk(acc[2*j], uA0, uA1); upk(acc[2*j + 1], uB0, uB1);
            float tA0 = xla_tanh(__fadd_rn(uA0, bb));
            float tA1 = xla_tanh(__fadd_rn(uA1, bb));
            float tB0 = xla_tanh(__fadd_rn(uB0, bb));
            float tB1 = xla_tanh(__fadd_rn(uB1, bb));
            ull* op = su + S2U + (co * R2 + rr) * PW + 1;
            op[pA] = pk(tA0, tA1);
            op[pB] = pk(tB0, tB1);
            if (pA == 15) op[-1] = pk(tB1, tB0);
            if (pA == 0)  op[32] = pk(tA1, tA0);
        }
    }
    // pass 2: rows 16..17, 1pp x 2co: 2*32*8 = 512 tasks
    if (tid < 512) {
        int rr = 16 + (tid >> 8), rem = tid & 255;
        int p0 = rem >> 3;
        int coB = (rem & 7) << 1;
        ull acc0 = 0ull, acc1 = 0ull;
        #pragma unroll
        for (int dy = 0; dy < 3; dy++) {
            const ull* rbp = su + S1U + (rr + dy) * PW + 1;
            #pragma unroll
            for (int dx = 0; dx < 3; dx++) {
                const ull* wb = su + WU1 + (dy * 3 + dx) * 256 + coB;
                #pragma unroll 4
                for (int ci = 0; ci < 16; ci++) {
                    const ull* rp = rbp + ci * (R1 * PW);
                    ull qa = rp[p0 + dx - 1];
                    ulonglong2 wv = *(const ulonglong2*)(wb + ci * 16);
                    fma2(acc0, wv.x, qa);
                    fma2(acc1, wv.y, qa);
                }
            }
        }
        #pragma unroll
        for (int j = 0; j < 2; j++) {
            int co = coB + j;
            float bb = sb[16 + co];
            float u0, u1;
            upk(j == 0 ? acc0 : acc1, u0, u1);
            float t0 = xla_tanh(__fadd_rn(u0, bb));
            float t1 = xla_tanh(__fadd_rn(u1, bb));
            ull* op = su + S2U + (co * R2 + rr) * PW + 1;
            op[p0] = pk(t0, t1);
            if (p0 == 31) op[-1] = pk(t1, t0);
            if (p0 == 0)  op[32] = pk(t1, t0);
        }
    }
    __syncthreads();

    // ---- Phase 3: conv3 (16 -> 1), chain (dy,dx,ci), bias, STE sign update ----
    // 512 tasks: 16 rows x 32 pairs; pair p0 covers columns (p0, p0+32)
    if (tid < TH * 32) {
        int rr = tid >> 5;
        int p0 = tid & 31;
        ull acc = 0ull;
        #pragma unroll
        for (int dy = 0; dy < 3; dy++) {
            const ull* rbp = su + S2U + (rr + dy) * PW + 1;
            #pragma unroll
            for (int dx = 0; dx < 3; dx++) {
                const ull* wp = su + WU2 + (dy * 3 + dx) * 16;
                #pragma unroll 4
                for (int ci = 0; ci < 16; ci++) {
                    const ull* rp = rbp + ci * (R2 * PW);
                    fma2(acc, wp[ci], rp[p0 + dx - 1]);
                }
            }
        }
        float bb = sb[32];
        float u0, u1;
        upk(acc, u0, u1);
        float l0 = __fadd_rn(u0, bb);
        float l1 = __fadd_rn(u1, bb);
        int gr = rbase + rr;
        // columns p0 and p0+32 share parity -> uniform condition per thread
        if (((gr + p0) & 1) != parity) {
            float* row = x + xbase + (gr << 6);
            float s0 = (l0 > 0.0f) ? 1.0f : ((l0 < 0.0f) ? -1.0f : 0.0f);
            float s1v = (l1 > 0.0f) ? 1.0f : ((l1 < 0.0f) ? -1.0f : 0.0f);
            // STE forward exactly as XLA computes it: l + (sign(l) - l)
            float m0 = __fadd_rn(l0, __fadd_rn(s0, -l0));
            float m1 = __fadd_rn(l1, __fadd_rn(s1v, -l1));
            row[p0]      = __fmul_rn(row[p0],      m0);
            row[p0 + 32] = __fmul_rn(row[p0 + 32], m1);
        }
    }
}

extern "C" void kernel_launch(void* const* d_in, const int* in_sizes, int n_in,
                              void* d_out, int out_size)
{
    const float* z  = (const float*)d_in[0];
    const float* W0 = (const float*)d_in[1];
    const float* b0 = (const float*)d_in[2];
    const float* W1 = (const float*)d_in[3];
    const float* b1 = (const float*)d_in[4];
    const float* W2 = (const float*)d_in[5];
    const float* b2 = (const float*)d_in[6];
    float* x = (float*)d_out;

    cudaFuncSetAttribute(layer_kernel, cudaFuncAttributeMaxDynamicSharedMemorySize,
                         (int)SMEM_BYTES);

    // reset working state each replay: x <- z
    copy_k<<<(Bg * Lg * Lg) / (4 * 256), 256>>>((const float4*)z, (float4*)x);

    for (int i = 0; i < 4; i++) {
        layer_kernel<<<dim3(NTILES, Bg), THREADS, SMEM_BYTES>>>(
            x,
            W0 + i * 144, b0 + i * 16,
            W1 + i * 2304, b1 + i * 16,
            W2 + i * 144, b2 + i,
            i & 1);
    }
}

// round 6
// speedup vs baseline: 1.5112x; 1.5112x over previous
#include <cuda_runtime.h>

typedef unsigned long long ull;

#define Lg 64
#define Bg 1024
#define TH 16
#define NTILES (Lg/TH)          // 4
#define THREADS 640
#define R1 (TH+4)               // 20 conv1 output rows (halo 2)
#define R2 (TH+2)               // 18 conv2 output rows (halo 1)
#define RZ (TH+6)               // 22 input rows (halo 3)
#define PW 34                   // pairs per row: p = -1..32 (wrapped halo)

// ---- shared memory layout (ull units) ----
#define S1U 0                               // 16*20*34 = 10880
#define S2U (S1U + 16*R1*PW)                // 10880 (+9792)
#define SZU (S2U + 16*R2*PW)                // 20672 (+748)
#define WU1 (SZU + RZ*PW)                   // 21420 (2304)
#define WU0 (WU1 + 2304)                    // 23724 (144)
#define WU2 (WU0 + 144)                     // 23868 (144)
#define BFU (WU2 + 144)                     // 24012 (biases: 33 floats -> 20 ull)
#define U_TOTAL (BFU + 20)                  // 24032
#define SMEM_BYTES ((size_t)U_TOTAL * 8)    // 192256 B

// ---- packed f32x2 helpers (sm_100+) : per-lane exact fp32 FMA ----
__device__ __forceinline__ ull pk(float lo, float hi) {
    ull r; asm("mov.b64 %0, {%1, %2};" : "=l"(r) : "f"(lo), "f"(hi)); return r;
}
__device__ __forceinline__ void upk(ull v, float& lo, float& hi) {
    asm("mov.b64 {%0, %1}, %2;" : "=f"(lo), "=f"(hi) : "l"(v));
}
__device__ __forceinline__ void fma2(ull& d, ull a, ull b) {
    asm("fma.rn.f32x2 %0, %1, %2, %0;" : "+l"(d) : "l"(a), "l"(b));
}

// XLA EmitFastTanh replica. DO NOT CHANGE (bit-exactness verified).
__device__ __forceinline__ float xla_tanh(float x) {
    float ax = fabsf(x);
    float xc = fminf(fmaxf(x, -9.0f), 9.0f);
    float x2 = __fmul_rn(xc, xc);
    float p = -2.76076847742355e-16f;
    p = __fmaf_rn(p, x2,  2.00018790482477e-13f);
    p = __fmaf_rn(p, x2, -8.60467152213735e-11f);
    p = __fmaf_rn(p, x2,  5.12229709037114e-08f);
    p = __fmaf_rn(p, x2,  1.48572235717979e-05f);
    p = __fmaf_rn(p, x2,  6.37261928875436e-04f);
    p = __fmaf_rn(p, x2,  4.89352455891786e-03f);
    float num = __fmul_rn(xc, p);
    float q =  1.19825839466702e-06f;
    q = __fmaf_rn(q, x2,  1.18534705686654e-04f);
    q = __fmaf_rn(q, x2,  2.26843463243900e-03f);
    q = __fmaf_rn(q, x2,  4.89352518554385e-03f);
    float r = __fdiv_rn(num, q);
    return (ax < 0.0004f) ? x : r;
}

__global__ void copy_k(const float4* __restrict__ in, float4* __restrict__ out) {
    int i = blockIdx.x * blockDim.x + threadIdx.x;
    out[i] = in[i];
}

// One fused layer. All conv accumulations are single fp32 FMA chains from 0
// in k = (dy, dx, ci) order (ci fastest), bias after — bit-identical to XLA.
__global__ void __launch_bounds__(THREADS, 1)
layer_kernel(float* __restrict__ x,
             const float* __restrict__ w0, const float* __restrict__ b0,
             const float* __restrict__ w1, const float* __restrict__ b1,
             const float* __restrict__ w2, const float* __restrict__ b2,
             int parity)
{
    extern __shared__ ull su[];
    float* sb = (float*)(su + BFU);      // sb[0..15]=b0, [16..31]=b1, [32]=b2

    const int tid   = threadIdx.x;
    const int rbase = blockIdx.x * TH;                 // even
    const int xbase = ((int)blockIdx.y) << 12;         // b*4096

    // ---- Phase 0: weights as duplicated (w,w) pairs + biases + packed input ----
    for (int t = tid; t < 2304; t += THREADS) { float w = w1[t]; su[WU1 + t] = pk(w, w); }
    if (tid < 144) {
        float a = w0[tid], b = w2[tid];
        su[WU0 + tid] = pk(a, a);
        su[WU2 + tid] = pk(b, b);
    }
    if (tid >= 160 && tid < 176) { int i = tid - 160; sb[i] = b0[i]; }
    if (tid >= 192 && tid < 208) { int i = tid - 192; sb[16 + i] = b1[i]; }
    if (tid == 224) { sb[32] = b2[0]; }

    // packed masked input: entry e of row rr holds pair p = e-1:
    // ( z[gr][p&63], z[gr][(p+32)&63] ), zeroed at non-A sites.
    for (int t = tid; t < RZ * PW; t += THREADS) {
        int rr = t / PW, e = t - rr * PW, p = e - 1;
        int gr = (rbase + rr - 3) & 63;
        int c0 = p & 63, c1 = (p + 32) & 63;
        const float* row = x + xbase + (gr << 6);
        float v0 = row[c0], v1 = row[c1];
        v0 = (((gr + c0) & 1) == parity) ? v0 : 0.0f;
        v1 = (((gr + c1) & 1) == parity) ? v1 : 0.0f;
        su[SZU + t] = pk(v0, v1);
    }
    __syncthreads();

    // ---- Phase 1: conv1 (1 -> 16), chain (dy,dx), bias, tanh ----
    // EXACTLY 640 tasks: 20 rows x 16 pair-lanes x 2 co-halves (one per thread)
    {
        int rr = tid >> 5, rem = tid & 31;
        int pA = rem & 15, pB = pA + 16;
        int coB = (rem >> 4) << 3;
        ull acc[16];
        #pragma unroll
        for (int i = 0; i < 16; i++) acc[i] = 0ull;
        #pragma unroll
        for (int dy = 0; dy < 3; dy++) {
            const ull* rp = su + SZU + (rr + dy) * PW + 1;
            #pragma unroll
            for (int dx = 0; dx < 3; dx++) {
                ull qa = rp[pA + dx - 1];
                ull qb = rp[pB + dx - 1];
                const ull* wp = su + WU0 + (dy * 3 + dx) * 16 + coB;
                #pragma unroll
                for (int j = 0; j < 4; j++) {
                    ulonglong2 wv = *(const ulonglong2*)(wp + 2 * j);
                    fma2(acc[4*j + 0], wv.x, qa);
                    fma2(acc[4*j + 1], wv.x, qb);
                    fma2(acc[4*j + 2], wv.y, qa);
                    fma2(acc[4*j + 3], wv.y, qb);
                }
            }
        }
        #pragma unroll
        for (int j = 0; j < 8; j++) {
            int co = coB + j;
            float bb = sb[co];
            ull aA = acc[((j >> 1) << 2) + ((j & 1) << 1)];
            ull aB = acc[((j >> 1) << 2) + ((j & 1) << 1) + 1];
            float uA0, uA1, uB0, uB1;
            upk(aA, uA0, uA1); upk(aB, uB0, uB1);
            float tA0 = xla_tanh(__fadd_rn(uA0, bb));
            float tA1 = xla_tanh(__fadd_rn(uA1, bb));
            float tB0 = xla_tanh(__fadd_rn(uB0, bb));
            float tB1 = xla_tanh(__fadd_rn(uB1, bb));
            ull* op = su + S1U + (co * R1 + rr) * PW + 1;
            op[pA] = pk(tA0, tA1);
            op[pB] = pk(tB0, tB1);
            if (pA == 15) op[-1] = pk(tB1, tB0);   // halo = swap(pair 31)
            if (pA == 0)  op[32] = pk(tA1, tA0);   // halo = swap(pair 0)
        }
    }
    __syncthreads();

    // ---- Phase 2: conv2 (16 -> 16), chain (dy,dx,ci), bias, tanh ----
    // main: rows 0..17, 576 tasks: 18 rows x 16 pair-lanes x 2 co-halves
    if (tid < 576) {
        int rr = tid >> 5, rem = tid & 31;
        int pA = rem & 15, pB = pA + 16;
        int coB = (rem >> 4) << 3;
        ull acc[16];
        #pragma unroll
        for (int i = 0; i < 16; i++) acc[i] = 0ull;
        #pragma unroll
        for (int dy = 0; dy < 3; dy++) {
            const ull* rbp = su + S1U + (rr + dy) * PW + 1;
            #pragma unroll
            for (int dx = 0; dx < 3; dx++) {
                const ull* wb = su + WU1 + (dy * 3 + dx) * 256 + coB;
                #pragma unroll 8
                for (int ci = 0; ci < 16; ci++) {
                    const ull* rp = rbp + ci * (R1 * PW);
                    ull qa = rp[pA + dx - 1];
                    ull qb = rp[pB + dx - 1];
                    const ull* wp = wb + ci * 16;
                    ulonglong2 w01 = *(const ulonglong2*)(wp);
                    ulonglong2 w23 = *(const ulonglong2*)(wp + 2);
                    fma2(acc[0], w01.x, qa); fma2(acc[1], w01.x, qb);
                    fma2(acc[2], w01.y, qa); fma2(acc[3], w01.y, qb);
                    fma2(acc[4], w23.x, qa); fma2(acc[5], w23.x, qb);
                    fma2(acc[6], w23.y, qa); fma2(acc[7], w23.y, qb);
                    // NOTE: acc[8..15] pattern continues below to keep 16 accs
                    const ull* wp2 = wp + 4;
                    ulonglong2 w45 = *(const ulonglong2*)(wp2);
                    ulonglong2 w67 = *(const ulonglong2*)(wp2 + 2);
                    fma2(acc[8],  w45.x, qa); fma2(acc[9],  w45.x, qb);
                    fma2(acc[10], w45.y, qa); fma2(acc[11], w45.y, qb);
                    fma2(acc[12], w67.x, qa); fma2(acc[13], w67.x, qb);
                    fma2(acc[14], w67.y, qa); fma2(acc[15], w67.y, qb);
                }
            }
        }
        #pragma unroll
        for (int j = 0; j < 8; j++) {
            int co = coB + j;
            float bb = sb[16 + co];
            ull aA = acc[2*j];
            ull aB = acc[2*j + 1];
            float uA0, uA1, uB0, uB1;
            upk(aA, uA0, uA1); upk(aB, uB0, uB1);
            float tA0 = xla_tanh(__fadd_rn(uA0, bb));
            float tA1 = xla_tanh(__fadd_rn(uA1, bb));
            float tB0 = xla_tanh(__fadd_rn(uB0, bb));
            float tB1 = xla_tanh(__fadd_rn(uB1, bb));
            ull* op = su + S2U + (co * R2 + rr) * PW + 1;
            op[pA] = pk(tA0, tA1);
            op[pB] = pk(tB0, tB1);
            if (pA == 15) op[-1] = pk(tB1, tB0);
            if (pA == 0)  op[32] = pk(tA1, tA0);
        }
    }
    __syncthreads();

    // ---- Phase 3: conv3 (16 -> 1), chain (dy,dx,ci), bias, STE sign update ----
    // 512 tasks: 16 rows x 32 pairs; pair p0 covers columns (p0, p0+32)
    if (tid < TH * 32) {
        int rr = tid >> 5;
        int p0 = tid & 31;
        ull acc = 0ull;
        #pragma unroll
        for (int dy = 0; dy < 3; dy++) {
            const ull* rbp = su + S2U + (rr + dy) * PW + 1;
            #pragma unroll
            for (int dx = 0; dx < 3; dx++) {
                const ull* wp = su + WU2 + (dy * 3 + dx) * 16;
                #pragma unroll 8
                for (int ci = 0; ci < 16; ci++) {
                    const ull* rp = rbp + ci * (R2 * PW);
                    fma2(acc, wp[ci], rp[p0 + dx - 1]);
                }
            }
        }
        float bb = sb[32];
        float u0, u1;
        upk(acc, u0, u1);
        float l0 = __fadd_rn(u0, bb);
        float l1 = __fadd_rn(u1, bb);
        int gr = rbase + rr;
        // columns p0 and p0+32 share parity -> uniform condition per thread
        if (((gr + p0) & 1) != parity) {
            float* row = x + xbase + (gr << 6);
            float s0 = (l0 > 0.0f) ? 1.0f : ((l0 < 0.0f) ? -1.0f : 0.0f);
            float s1v = (l1 > 0.0f) ? 1.0f : ((l1 < 0.0f) ? -1.0f : 0.0f);
            // STE forward exactly as XLA computes it: l + (sign(l) - l)
            float m0 = __fadd_rn(l0, __fadd_rn(s0, -l0));
            float m1 = __fadd_rn(l1, __fadd_rn(s1v, -l1));
            row[p0]      = __fmul_rn(row[p0],      m0);
            row[p0 + 32] = __fmul_rn(row[p0 + 32], m1);
        }
    }
}

extern "C" void kernel_launch(void* const* d_in, const int* in_sizes, int n_in,
                              void* d_out, int out_size)
{
    const float* z  = (const float*)d_in[0];
    const float* W0 = (const float*)d_in[1];
    const float* b0 = (const float*)d_in[2];
    const float* W1 = (const float*)d_in[3];
    const float* b1 = (const float*)d_in[4];
    const float* W2 = (const float*)d_in[5];
    const float* b2 = (const float*)d_in[6];
    float* x = (float*)d_out;

    cudaFuncSetAttribute(layer_kernel, cudaFuncAttributeMaxDynamicSharedMemorySize,
                         (int)SMEM_BYTES);

    // reset working state each replay: x <- z
    copy_k<<<(Bg * Lg * Lg) / (4 * 256), 256>>>((const float4*)z, (float4*)x);

    for (int i = 0; i < 4; i++) {
        layer_kernel<<<dim3(NTILES, Bg), THREADS, SMEM_BYTES>>>(
            x,
            W0 + i * 144, b0 + i * 16,
            W1 + i * 2304, b1 + i * 16,
            W2 + i * 144, b2 + i,
            i & 1);
    }
}